// round 11
// baseline (speedup 1.0000x reference)
#include <cuda_runtime.h>
#include <cuda_fp16.h>
#include <cstdint>
#include <math.h>

#define HH 128
#define WW 128
#define HW (HH*WW)
#define CB 64
#define BB 16

// ---------------- scratch (no cudaMalloc allowed) ----------------
__device__ uint2 g_wmh[BB*2*4*9*4*32];           // main weights [b][z][cc][k][nt4][lane]
__device__ uint2 g_wsh[4*9*2*32];                // SE1 weights  [cc][k][nt2][lane]
__device__ uint2 g_ws2[9*32];                    // SE2 weights  [k][lane] (n=0 col only)
__device__ uint32_t g_hh[(size_t)BB*8*HW];       // SE hidden, half2 ci-pairs [b][cp8][pos]
__device__ float g_A[BB*HW];                     // spatial attention
__device__ float g_mean[BB*CB];                  // pooled means
__device__ uint32_t g_xh[(size_t)BB*32*HW];      // fp16 x, half2 ci-pairs: [b][cp32][pos]

__device__ __forceinline__ uint32_t pack_h2(float lo, float hi) {
    __half2 h = __floats2half2_rn(lo, hi);
    return *reinterpret_cast<uint32_t*>(&h);
}
__device__ __forceinline__ void mma16(float* d, const uint32_t* a, uint32_t b0, uint32_t b1) {
    asm volatile(
        "mma.sync.aligned.m16n8k16.row.col.f32.f16.f16.f32 "
        "{%0,%1,%2,%3}, {%4,%5,%6,%7}, {%8,%9}, {%0,%1,%2,%3};\n"
        : "+f"(d[0]), "+f"(d[1]), "+f"(d[2]), "+f"(d[3])
        : "r"(a[0]), "r"(a[1]), "r"(a[2]), "r"(a[3]), "r"(b0), "r"(b1));
}
__device__ __forceinline__ void cp16z(uint32_t dst, const void* src, bool p) {
    asm volatile("cp.async.cg.shared.global [%0], [%1], 16, %2;"
                 :: "r"(dst), "l"(src), "r"(p ? 16u : 0u));
}
__device__ __forceinline__ void cp16(uint32_t dst, const void* src) {
    asm volatile("cp.async.cg.shared.global [%0], [%1], 16;" :: "r"(dst), "l"(src));
}
#define CP_COMMIT() asm volatile("cp.async.commit_group;" ::: "memory")

__device__ __forceinline__ uint32_t smem_u32(const void* p) {
    uint32_t a;
    asm("{ .reg .u64 t; cvta.to.shared.u64 t, %1; cvt.u32.u64 %0, t; }" : "=r"(a) : "l"(p));
    return a;
}

// ---------------- stage 1: fp16 pack (ci-pairs) + global average pool ----------------
__global__ void __launch_bounds__(256) convert_pool(const float* __restrict__ x) {
    int cp = blockIdx.x, b = blockIdx.y, t = threadIdx.x;
    const float4* p0 = (const float4*)(x + ((size_t)(b * 64 + 2 * cp)) * HW);
    const float4* p1 = p0 + HW / 4;
    uint4* o = (uint4*)(g_xh + ((size_t)(b * 32 + cp)) * HW);
    float s0 = 0.f, s1 = 0.f;
    #pragma unroll 4
    for (int i = t; i < HW / 4; i += 256) {
        float4 a = p0[i], c = p1[i];
        s0 += (a.x + a.y) + (a.z + a.w);
        s1 += (c.x + c.y) + (c.z + c.w);
        uint4 w;
        w.x = pack_h2(a.x, c.x);
        w.y = pack_h2(a.y, c.y);
        w.z = pack_h2(a.z, c.z);
        w.w = pack_h2(a.w, c.w);
        o[i] = w;
    }
    #pragma unroll
    for (int off = 16; off; off >>= 1) {
        s0 += __shfl_xor_sync(0xffffffffu, s0, off);
        s1 += __shfl_xor_sync(0xffffffffu, s1, off);
    }
    __shared__ float ws0[8], ws1[8];
    if ((t & 31) == 0) { ws0[t >> 5] = s0; ws1[t >> 5] = s1; }
    __syncthreads();
    if (t == 0) {
        float a0 = 0.f, a1 = 0.f;
        #pragma unroll
        for (int i = 0; i < 8; i++) { a0 += ws0[i]; a1 += ws1[i]; }
        g_mean[b * CB + 2 * cp]     = a0 * (1.f / (float)HW);
        g_mean[b * CB + 2 * cp + 1] = a1 * (1.f / (float)HW);
    }
}

// ---------------- stage 2: FC chain + all weight builds (merged) ----------------
#define WM_PER_B (2*4*9*4*32)
#define WS_U2 (4*9*2*32)
__global__ void __launch_bounds__(1024) prep(const float* __restrict__ fc_w1,
                                             const float* __restrict__ fc_w2,
                                             const float* __restrict__ weight,
                                             const float* __restrict__ se_w1,
                                             const float* __restrict__ se_w2) {
    int b = blockIdx.x, t = threadIdx.x;
    __shared__ float smean[64];
    __shared__ float sh[4];
    __shared__ float sy[576];
    if (t < 64) smean[t] = g_mean[b * 64 + t];
    __syncthreads();
    if (t < 4) {
        float s = 0.f;
        #pragma unroll
        for (int c = 0; c < 64; c++) s += smean[c] * fc_w1[t * 64 + c];
        sh[t] = fmaxf(s, 0.f);
    }
    __syncthreads();
    if (t < 576) {
        float s = 0.f;
        #pragma unroll
        for (int r = 0; r < 4; r++) s += sh[r] * fc_w2[t * 4 + r];
        sy[t] = 1.f / (1.f + expf(-s));
    }
    __syncthreads();
    for (int idx = t; idx < WM_PER_B; idx += 1024) {
        int lane = idx & 31;
        int nt   = (idx >> 5) & 3;
        int k    = (idx >> 7) % 9;
        int rem  = (idx >> 7) / 9;
        int cc   = rem & 3;
        int z    = rem >> 2;
        int g = lane >> 2, tig = lane & 3;
        int co = z * 32 + nt * 8 + g, ci0 = cc * 16;
        float w0 = weight[(co * 64 + ci0 + 2*tig    ) * 9 + k] * sy[(ci0 + 2*tig    ) * 9 + k];
        float w1 = weight[(co * 64 + ci0 + 2*tig + 1) * 9 + k] * sy[(ci0 + 2*tig + 1) * 9 + k];
        float w2 = weight[(co * 64 + ci0 + 2*tig + 8) * 9 + k] * sy[(ci0 + 2*tig + 8) * 9 + k];
        float w3 = weight[(co * 64 + ci0 + 2*tig + 9) * 9 + k] * sy[(ci0 + 2*tig + 9) * 9 + k];
        g_wmh[(size_t)b * WM_PER_B + idx] = make_uint2(pack_h2(w0, w1), pack_h2(w2, w3));
    }
    if (b == 0) {
        for (int j = t; j < WS_U2; j += 1024) {
            int lane = j & 31;
            int nt   = (j >> 5) & 1;
            int k    = (j >> 6) % 9;
            int cc   = (j >> 6) / 9;
            int g = lane >> 2, tig = lane & 3;
            int co = nt * 8 + g, ci0 = cc * 16;
            float w0 = se_w1[(co * 64 + ci0 + 2*tig    ) * 9 + k];
            float w1 = se_w1[(co * 64 + ci0 + 2*tig + 1) * 9 + k];
            float w2 = se_w1[(co * 64 + ci0 + 2*tig + 8) * 9 + k];
            float w3 = se_w1[(co * 64 + ci0 + 2*tig + 9) * 9 + k];
            g_wsh[j] = make_uint2(pack_h2(w0, w1), pack_h2(w2, w3));
        }
        if (t < 9 * 32) {
            int k = t >> 5, lane = t & 31;
            int g = lane >> 2, tig = lane & 3;
            float w0 = 0.f, w1 = 0.f, w2 = 0.f, w3 = 0.f;
            if (g == 0) {
                w0 = se_w2[(2*tig    ) * 9 + k];
                w1 = se_w2[(2*tig + 1) * 9 + k];
                w2 = se_w2[(2*tig + 8) * 9 + k];
                w3 = se_w2[(2*tig + 9) * 9 + k];
            }
            g_ws2[t] = make_uint2(pack_h2(w0, w1), pack_h2(w2, w3));
        }
    }
}

// ---------------- fp16 mma direct conv, mt=4 warps, 256 thr, 2 CTA/SM ----------------
// CTA: batch b (blockIdx.y), 4 rows R0..R0+3 (blockIdx.x), co half z (blockIdx.z, MODE 0).
// 256 thr = 8 warps; warp w: row pair rp=w>>2 (rows rp*2, rp*2+1), colband (w&3)*32.
// Per warp: mt=4 m16-tiles (2 rows x 2 col-halves) x NT n-tiles -> 192 B smem / mma (NT=4).
// sx: [cp8][row6][word136], halo words 3 & 132 pre-zeroed; cp stride 824 (conflict-free).
// sw: [k][nt][lane] uint2 B-fragment; LDS.64 at index nt*32+lane (conflict-free).
#define SX_W 6592               // 8 * 824

template<int NT, int MODE>   // MODE 0: main conv half (*A -> out), 1: se conv1 (relu -> g_hh)
__global__ void __launch_bounds__(256, 2) conv_mma(float* __restrict__ outp) {
    constexpr int SW_W = 9 * NT * 64;
    constexpr int BUF_W = SX_W + SW_W;
    extern __shared__ uint32_t sm[];
    const uint32_t smb = smem_u32(sm);
    const int tid = threadIdx.x, wid = tid >> 5, lane = tid & 31;
    const int g = lane >> 2, tig = lane & 3;
    const int b = blockIdx.y, R0 = blockIdx.x * 4;
    const int zz = (MODE == 0) ? blockIdx.z : 0;
    const int co_base = zz * 32;
    const int rp = wid >> 2, colbase = (wid & 3) * 32;

    // x-staging geometry: 48 (cp,row) slots x 4 col-quarters (32 words each)
    const int sr = tid >> 2, q = tid & 3;
    const int cp_x = sr / 6, r_x = sr - cp_x * 6;
    const int gy = R0 - 1 + r_x;
    const bool xact = sr < 48;
    const bool rowok = xact && ((unsigned)gy < (unsigned)HH);
    const uint32_t* xrow = g_xh + ((size_t)(b * 32 + cp_x)) * HW + (ptrdiff_t)gy * WW + q * 32;
    const uint32_t dxoff = (uint32_t)(cp_x * 824 + r_x * 136 + 4 + q * 32) * 4;

    // one-time halo zero (words 3 and 132 of every (cp,row), both buffers)
    if (xact && q == 0) {
        #pragma unroll
        for (int bi = 0; bi < 2; bi++) {
            sm[bi * BUF_W + cp_x * 824 + r_x * 136 + 3]   = 0;
            sm[bi * BUF_W + cp_x * 824 + r_x * 136 + 132] = 0;
        }
    }

    auto stage = [&](int cc, int bufi) {
        const uint32_t bufb = smb + (uint32_t)bufi * (BUF_W * 4);
        if (xact) {
            const uint32_t* src = xrow + (size_t)(cc * 8) * HW;
            const uint32_t dst = bufb + dxoff;
            #pragma unroll
            for (int j = 0; j < 8; j++)
                cp16z(dst + j * 16, src + j * 4, rowok);
        }
        const uint4* wsrc = (const uint4*)((MODE == 0)
            ? g_wmh + (size_t)(((b * 2 + zz) * 4 + cc)) * (SW_W / 2)
            : g_wsh + (size_t)cc * (SW_W / 2));
        constexpr int QUADS = SW_W / 4;        // 576 (NT=4) or 288 (NT=2)
        #pragma unroll
        for (int it = 0; it < (QUADS + 255) / 256; it++) {
            int idx = tid + it * 256;
            if (QUADS % 256 == 0 || idx < QUADS)
                cp16(bufb + (uint32_t)(SX_W + idx * 4) * 4, wsrc + idx);
        }
    };

    float d[2][2][NT][4];   // [row r][col-half m][nt][frag]
    #pragma unroll
    for (int r = 0; r < 2; r++)
        #pragma unroll
        for (int m = 0; m < 2; m++)
            #pragma unroll
            for (int nt = 0; nt < NT; nt++)
                #pragma unroll
                for (int j = 0; j < 4; j++) d[r][m][nt][j] = 0.f;

    stage(0, 0);
    CP_COMMIT();

    for (int cc = 0; cc < 4; ++cc) {
        if (cc < 3) {
            stage(cc + 1, (cc + 1) & 1);
            CP_COMMIT();
            asm volatile("cp.async.wait_group 1;" ::: "memory");
        } else {
            asm volatile("cp.async.wait_group 0;" ::: "memory");
        }
        __syncthreads();

        const uint32_t* sxp = sm + (cc & 1) * BUF_W;
        const uint32_t* swp = sxp + SX_W;

        #pragma unroll
        for (int k = 0; k < 9; ++k) {
            const int dy = k / 3, dx = k % 3;
            uint32_t af[2][2][4];
            #pragma unroll
            for (int r = 0; r < 2; ++r) {
                const int rowoff = tig * 824 + (rp * 2 + r + dy) * 136;
                #pragma unroll
                for (int m = 0; m < 2; ++m) {
                    const int b0 = rowoff + colbase + m * 16 + g + dx + 3;
                    af[r][m][0] = sxp[b0];
                    af[r][m][1] = sxp[b0 + 8];
                    af[r][m][2] = sxp[b0 + 4 * 824];
                    af[r][m][3] = sxp[b0 + 4 * 824 + 8];
                }
            }
            const uint2* swq = (const uint2*)(swp + k * (NT * 64)) + lane;
            #pragma unroll
            for (int nt = 0; nt < NT; ++nt) {
                uint2 w2 = swq[nt * 32];
                mma16(d[0][0][nt], af[0][0], w2.x, w2.y);
                mma16(d[0][1][nt], af[0][1], w2.x, w2.y);
                mma16(d[1][0][nt], af[1][0], w2.x, w2.y);
                mma16(d[1][1][nt], af[1][1], w2.x, w2.y);
            }
        }
        __syncthreads();
    }

    // epilogue
    #pragma unroll
    for (int r = 0; r < 2; ++r) {
        const int grow = R0 + rp * 2 + r;
        #pragma unroll
        for (int m = 0; m < 2; ++m) {
            const int col = colbase + m * 16 + g;
            float av0 = 1.f, av1 = 1.f;
            if (MODE == 0) {
                av0 = g_A[b * HW + grow * WW + col];
                av1 = g_A[b * HW + grow * WW + col + 8];
            }
            #pragma unroll
            for (int nt = 0; nt < NT; ++nt) {
                if (MODE == 0) {
                    const int co = co_base + nt * 8 + tig * 2;
                    float* o0 = outp + ((size_t)(b * 64 + co)) * HW + grow * WW + col;
                    float* o1 = o0 + HW;
                    o0[0] = d[r][m][nt][0] * av0;
                    o1[0] = d[r][m][nt][1] * av0;
                    o0[8] = d[r][m][nt][2] * av1;
                    o1[8] = d[r][m][nt][3] * av1;
                } else {
                    const int cp = nt * 4 + tig;
                    uint32_t* hh = g_hh + ((size_t)(b * 8 + cp)) * HW + grow * WW + col;
                    hh[0] = pack_h2(fmaxf(d[r][m][nt][0], 0.f), fmaxf(d[r][m][nt][1], 0.f));
                    hh[8] = pack_h2(fmaxf(d[r][m][nt][2], 0.f), fmaxf(d[r][m][nt][3], 0.f));
                }
            }
        }
    }
}

// ---------------- SE conv2 via mma (16 -> 1, sigmoid) -> g_A ----------------
__global__ void __launch_bounds__(512, 2) se2_mma() {
    extern __shared__ uint32_t sm[];
    const uint32_t smb = smem_u32(sm);
    const int tid = threadIdx.x, wid = tid >> 5, lane = tid & 31;
    const int g = lane >> 2, tig = lane & 3;
    const int b = blockIdx.y, R0 = blockIdx.x * 4;
    const int prow = wid >> 2, colbase = (wid & 3) * 32;

    uint2 wf[9];
    #pragma unroll
    for (int k = 0; k < 9; k++) wf[k] = g_ws2[k * 32 + lane];

    const int sr = tid >> 3, q = tid & 7;
    const int cp_x = sr / 6, r_x = sr - cp_x * 6;
    const int gy = R0 - 1 + r_x;
    const bool xact = sr < 48;
    const bool rowok = xact && ((unsigned)gy < (unsigned)HH);

    if (xact && q == 0) {
        sm[cp_x * 824 + r_x * 136 + 3]   = 0;
        sm[cp_x * 824 + r_x * 136 + 132] = 0;
    }
    if (xact) {
        const uint32_t* src = g_hh + ((size_t)(b * 8 + cp_x)) * HW + (ptrdiff_t)gy * WW + q * 16;
        const uint32_t dst = smb + (uint32_t)(cp_x * 824 + r_x * 136 + 4 + q * 16) * 4;
        #pragma unroll
        for (int j = 0; j < 4; j++)
            cp16z(dst + j * 16, src + j * 4, rowok);
    }
    CP_COMMIT();
    asm volatile("cp.async.wait_group 0;" ::: "memory");
    __syncthreads();

    float d[2][4] = {};
    #pragma unroll
    for (int k = 0; k < 9; ++k) {
        const int dy = k / 3, dx = k % 3;
        #pragma unroll
        for (int mt = 0; mt < 2; ++mt) {
            const int colb = colbase + mt * 16 + g + dx + 3;
            const int b0 = tig * 824 + (prow + dy) * 136 + colb;
            uint32_t af[4];
            af[0] = sm[b0];
            af[1] = sm[b0 + 8];
            af[2] = sm[b0 + 4 * 824];
            af[3] = sm[b0 + 4 * 824 + 8];
            mma16(d[mt], af, wf[k].x, wf[k].y);
        }
    }

    if (tig == 0) {
        const int grow = R0 + prow;
        #pragma unroll
        for (int mt = 0; mt < 2; ++mt) {
            const int col = colbase + mt * 16 + g;
            float* ap = g_A + b * HW + grow * WW + col;
            ap[0] = 1.f / (1.f + expf(-d[mt][0]));
            ap[8] = 1.f / (1.f + expf(-d[mt][2]));
        }
    }
}

extern "C" void kernel_launch(void* const* d_in, const int* in_sizes, int n_in,
                              void* d_out, int out_size) {
    const float* x      = (const float*)d_in[0];
    const float* weight = (const float*)d_in[1];
    const float* se_w1  = (const float*)d_in[2];
    const float* se_w2  = (const float*)d_in[3];
    const float* fc_w1  = (const float*)d_in[4];
    const float* fc_w2  = (const float*)d_in[5];
    float* out = (float*)d_out;

    const int smem_main = 2 * (SX_W + 9 * 4 * 64) * 4;   // 71.2 KB -> 2 CTAs/SM
    const int smem_se   = 2 * (SX_W + 9 * 2 * 64) * 4;   // 62.0 KB -> 2 CTAs/SM
    const int smem_se2  = SX_W * 4;                       // 26.4 KB
    cudaFuncSetAttribute((const void*)conv_mma<4,0>,
                         cudaFuncAttributeMaxDynamicSharedMemorySize, smem_main);
    cudaFuncSetAttribute((const void*)conv_mma<2,1>,
                         cudaFuncAttributeMaxDynamicSharedMemorySize, smem_se);
    cudaFuncSetAttribute((const void*)se2_mma,
                         cudaFuncAttributeMaxDynamicSharedMemorySize, smem_se2);

    convert_pool<<<dim3(32, BB), 256>>>(x);                          // g_xh + g_mean
    prep<<<BB, 1024>>>(fc_w1, fc_w2, weight, se_w1, se_w2);          // y + all weight frags
    conv_mma<2,1><<<dim3(32, BB), 256, smem_se>>>(nullptr);          // SE conv1 -> g_hh (fp16)
    se2_mma<<<dim3(32, BB), 512, smem_se2>>>();                      // SE conv2 -> g_A
    conv_mma<4,0><<<dim3(32, BB, 2), 256, smem_main>>>(out);         // main conv * A -> out
}

// round 12
// speedup vs baseline: 1.0426x; 1.0426x over previous
#include <cuda_runtime.h>
#include <cuda_fp16.h>
#include <cstdint>
#include <math.h>

#define HH 128
#define WW 128
#define HW (HH*WW)
#define CB 64
#define BB 16

// ---------------- scratch (no cudaMalloc allowed) ----------------
__device__ uint2 g_wmh[BB*2*4*9*4*32];           // main weights [b][z][cc][k][nt4][lane]
__device__ uint2 g_wsh[4*9*2*32];                // SE1 weights  [cc][k][nt2][lane]
__device__ uint2 g_ws2[9*32];                    // SE2 weights  [k][lane] (n=0 col only)
__device__ uint32_t g_hh[(size_t)BB*8*HW];       // SE hidden, half2 ci-pairs [b][cp8][pos]
__device__ float g_mean[BB*CB];                  // pooled means
__device__ uint32_t g_xh[(size_t)BB*32*HW];      // fp16 x, half2 ci-pairs: [b][cp32][pos]

__device__ __forceinline__ uint32_t pack_h2(float lo, float hi) {
    __half2 h = __floats2half2_rn(lo, hi);
    return *reinterpret_cast<uint32_t*>(&h);
}
__device__ __forceinline__ void mma16(float* d, const uint32_t* a, uint32_t b0, uint32_t b1) {
    asm volatile(
        "mma.sync.aligned.m16n8k16.row.col.f32.f16.f16.f32 "
        "{%0,%1,%2,%3}, {%4,%5,%6,%7}, {%8,%9}, {%0,%1,%2,%3};\n"
        : "+f"(d[0]), "+f"(d[1]), "+f"(d[2]), "+f"(d[3])
        : "r"(a[0]), "r"(a[1]), "r"(a[2]), "r"(a[3]), "r"(b0), "r"(b1));
}
__device__ __forceinline__ void cp16z(uint32_t dst, const void* src, bool p) {
    asm volatile("cp.async.cg.shared.global [%0], [%1], 16, %2;"
                 :: "r"(dst), "l"(src), "r"(p ? 16u : 0u));
}
__device__ __forceinline__ void cp16(uint32_t dst, const void* src) {
    asm volatile("cp.async.cg.shared.global [%0], [%1], 16;" :: "r"(dst), "l"(src));
}
#define CP_COMMIT() asm volatile("cp.async.commit_group;" ::: "memory")

__device__ __forceinline__ uint32_t smem_u32(const void* p) {
    uint32_t a;
    asm("{ .reg .u64 t; cvta.to.shared.u64 t, %1; cvt.u32.u64 %0, t; }" : "=r"(a) : "l"(p));
    return a;
}

// ---------------- stage 1: fp16 pack (ci-pairs) + global average pool ----------------
__global__ void __launch_bounds__(256) convert_pool(const float* __restrict__ x) {
    int cp = blockIdx.x, b = blockIdx.y, t = threadIdx.x;
    const float4* p0 = (const float4*)(x + ((size_t)(b * 64 + 2 * cp)) * HW);
    const float4* p1 = p0 + HW / 4;
    uint4* o = (uint4*)(g_xh + ((size_t)(b * 32 + cp)) * HW);
    float s0 = 0.f, s1 = 0.f;
    #pragma unroll 4
    for (int i = t; i < HW / 4; i += 256) {
        float4 a = p0[i], c = p1[i];
        s0 += (a.x + a.y) + (a.z + a.w);
        s1 += (c.x + c.y) + (c.z + c.w);
        uint4 w;
        w.x = pack_h2(a.x, c.x);
        w.y = pack_h2(a.y, c.y);
        w.z = pack_h2(a.z, c.z);
        w.w = pack_h2(a.w, c.w);
        o[i] = w;
    }
    #pragma unroll
    for (int off = 16; off; off >>= 1) {
        s0 += __shfl_xor_sync(0xffffffffu, s0, off);
        s1 += __shfl_xor_sync(0xffffffffu, s1, off);
    }
    __shared__ float ws0[8], ws1[8];
    if ((t & 31) == 0) { ws0[t >> 5] = s0; ws1[t >> 5] = s1; }
    __syncthreads();
    if (t == 0) {
        float a0 = 0.f, a1 = 0.f;
        #pragma unroll
        for (int i = 0; i < 8; i++) { a0 += ws0[i]; a1 += ws1[i]; }
        g_mean[b * CB + 2 * cp]     = a0 * (1.f / (float)HW);
        g_mean[b * CB + 2 * cp + 1] = a1 * (1.f / (float)HW);
    }
}

// ---------------- stage 2: FC chain + all weight builds (merged) ----------------
#define WM_PER_B (2*4*9*4*32)
#define WS_U2 (4*9*2*32)
__global__ void __launch_bounds__(1024) prep(const float* __restrict__ fc_w1,
                                             const float* __restrict__ fc_w2,
                                             const float* __restrict__ weight,
                                             const float* __restrict__ se_w1,
                                             const float* __restrict__ se_w2) {
    int b = blockIdx.x, t = threadIdx.x;
    __shared__ float smean[64];
    __shared__ float sh[4];
    __shared__ float sy[576];
    if (t < 64) smean[t] = g_mean[b * 64 + t];
    __syncthreads();
    if (t < 4) {
        float s = 0.f;
        #pragma unroll
        for (int c = 0; c < 64; c++) s += smean[c] * fc_w1[t * 64 + c];
        sh[t] = fmaxf(s, 0.f);
    }
    __syncthreads();
    if (t < 576) {
        float s = 0.f;
        #pragma unroll
        for (int r = 0; r < 4; r++) s += sh[r] * fc_w2[t * 4 + r];
        sy[t] = 1.f / (1.f + expf(-s));
    }
    __syncthreads();
    for (int idx = t; idx < WM_PER_B; idx += 1024) {
        int lane = idx & 31;
        int nt   = (idx >> 5) & 3;
        int k    = (idx >> 7) % 9;
        int rem  = (idx >> 7) / 9;
        int cc   = rem & 3;
        int z    = rem >> 2;
        int g = lane >> 2, tig = lane & 3;
        int co = z * 32 + nt * 8 + g, ci0 = cc * 16;
        float w0 = weight[(co * 64 + ci0 + 2*tig    ) * 9 + k] * sy[(ci0 + 2*tig    ) * 9 + k];
        float w1 = weight[(co * 64 + ci0 + 2*tig + 1) * 9 + k] * sy[(ci0 + 2*tig + 1) * 9 + k];
        float w2 = weight[(co * 64 + ci0 + 2*tig + 8) * 9 + k] * sy[(ci0 + 2*tig + 8) * 9 + k];
        float w3 = weight[(co * 64 + ci0 + 2*tig + 9) * 9 + k] * sy[(ci0 + 2*tig + 9) * 9 + k];
        g_wmh[(size_t)b * WM_PER_B + idx] = make_uint2(pack_h2(w0, w1), pack_h2(w2, w3));
    }
    if (b == 0) {
        for (int j = t; j < WS_U2; j += 1024) {
            int lane = j & 31;
            int nt   = (j >> 5) & 1;
            int k    = (j >> 6) % 9;
            int cc   = (j >> 6) / 9;
            int g = lane >> 2, tig = lane & 3;
            int co = nt * 8 + g, ci0 = cc * 16;
            float w0 = se_w1[(co * 64 + ci0 + 2*tig    ) * 9 + k];
            float w1 = se_w1[(co * 64 + ci0 + 2*tig + 1) * 9 + k];
            float w2 = se_w1[(co * 64 + ci0 + 2*tig + 8) * 9 + k];
            float w3 = se_w1[(co * 64 + ci0 + 2*tig + 9) * 9 + k];
            g_wsh[j] = make_uint2(pack_h2(w0, w1), pack_h2(w2, w3));
        }
        if (t < 9 * 32) {
            int k = t >> 5, lane = t & 31;
            int g = lane >> 2, tig = lane & 3;
            float w0 = 0.f, w1 = 0.f, w2 = 0.f, w3 = 0.f;
            if (g == 0) {
                w0 = se_w2[(2*tig    ) * 9 + k];
                w1 = se_w2[(2*tig + 1) * 9 + k];
                w2 = se_w2[(2*tig + 8) * 9 + k];
                w3 = se_w2[(2*tig + 9) * 9 + k];
            }
            g_ws2[t] = make_uint2(pack_h2(w0, w1), pack_h2(w2, w3));
        }
    }
}

// ---------------- fp16 mma direct conv (R10 config) + fused SE2 prologue ----------------
// CTA: batch b (blockIdx.y), 4 rows R0..R0+3 (blockIdx.x), co half z (blockIdx.z, MODE 0).
// N = NT*8 co per CTA. 512 thr = 16 warps. Chunk = 16 ci = 8 half2-pairs; 9 taps.
// MODE 0 prologue: stage hidden tile (g_hh) into buffer 0, run SE2 mma (N=8, n=0 valid),
// sigmoid -> sA smem [4][128]; epilogue multiplies by sA. No g_A global round-trip.
// sx: [cp8][row6][word136], halo words 3 & 132 pre-zeroed; cp stride 824 (conflict-free).
// sw: [k][nt][lane] uint2 B-fragment; LDS.64 at index nt*32+lane (conflict-free).
#define SX_W 6592               // 8 * 824

template<int NT, int MODE>   // MODE 0: main conv half (*A -> out), 1: se conv1 (relu -> g_hh)
__global__ void __launch_bounds__(512, 2) conv_mma(float* __restrict__ outp) {
    constexpr int SW_W = 9 * NT * 64;
    constexpr int BUF_W = SX_W + SW_W;
    extern __shared__ uint32_t sm[];
    const uint32_t smb = smem_u32(sm);
    float* sA = (float*)(sm + 2 * BUF_W);   // [4][128], MODE 0 only
    const int tid = threadIdx.x, wid = tid >> 5, lane = tid & 31;
    const int g = lane >> 2, tig = lane & 3;
    const int b = blockIdx.y, R0 = blockIdx.x * 4;
    const int zz = (MODE == 0) ? blockIdx.z : 0;
    const int co_base = zz * 32;
    const int prow = wid >> 2, colbase = (wid & 3) * 32;

    const int sr = tid >> 3, q = tid & 7;
    const int cp_x = sr / 6, r_x = sr - cp_x * 6;
    const int gy = R0 - 1 + r_x;
    const bool xact = sr < 48;
    const bool rowok = xact && ((unsigned)gy < (unsigned)HH);
    const uint32_t* xrow = g_xh + ((size_t)(b * 32 + cp_x)) * HW + (ptrdiff_t)gy * WW + q * 16;
    const uint32_t dxoff = (uint32_t)(cp_x * 824 + r_x * 136 + 4 + q * 16) * 4;

    // one-time halo zero (words 3 and 132 of every (cp,row), both buffers)
    if (xact && q == 0) {
        #pragma unroll
        for (int bi = 0; bi < 2; bi++) {
            sm[bi * BUF_W + cp_x * 824 + r_x * 136 + 3]   = 0;
            sm[bi * BUF_W + cp_x * 824 + r_x * 136 + 132] = 0;
        }
    }

    // ======== fused SE2 prologue (MODE 0): hidden tile -> A into sA ========
    if (MODE == 0) {
        uint2 wf[9];
        #pragma unroll
        for (int k = 0; k < 9; k++) wf[k] = g_ws2[k * 32 + lane];
        if (xact) {
            const uint32_t* src = g_hh + ((size_t)(b * 8 + cp_x)) * HW
                                  + (ptrdiff_t)gy * WW + q * 16;
            const uint32_t dst = smb + dxoff;   // buffer 0 sx region
            #pragma unroll
            for (int j = 0; j < 4; j++)
                cp16z(dst + j * 16, src + j * 4, rowok);
        }
        CP_COMMIT();
        asm volatile("cp.async.wait_group 0;" ::: "memory");
        __syncthreads();

        float d2[2][4] = {};
        #pragma unroll
        for (int k = 0; k < 9; ++k) {
            const int dy = k / 3, dx = k % 3;
            #pragma unroll
            for (int mt = 0; mt < 2; ++mt) {
                const int colb = colbase + mt * 16 + g + dx + 3;
                const int b0 = tig * 824 + (prow + dy) * 136 + colb;
                uint32_t af[4];
                af[0] = sm[b0];
                af[1] = sm[b0 + 8];
                af[2] = sm[b0 + 4 * 824];
                af[3] = sm[b0 + 4 * 824 + 8];
                mma16(d2[mt], af, wf[k].x, wf[k].y);
            }
        }
        if (tig == 0) {
            #pragma unroll
            for (int mt = 0; mt < 2; ++mt) {
                const int col = colbase + mt * 16 + g;
                sA[prow * 128 + col]     = 1.f / (1.f + expf(-d2[mt][0]));
                sA[prow * 128 + col + 8] = 1.f / (1.f + expf(-d2[mt][2]));
            }
        }
        __syncthreads();   // sA ready; buffer 0 free for x staging
    }
    // =======================================================================

    auto stage = [&](int cc, int bufi) {
        const uint32_t bufb = smb + (uint32_t)bufi * (BUF_W * 4);
        if (xact) {
            const uint32_t* src = xrow + (size_t)(cc * 8) * HW;
            const uint32_t dst = bufb + dxoff;
            #pragma unroll
            for (int j = 0; j < 4; j++)
                cp16z(dst + j * 16, src + j * 4, rowok);
        }
        const uint4* wsrc = (const uint4*)((MODE == 0)
            ? g_wmh + (size_t)(((b * 2 + zz) * 4 + cc)) * (SW_W / 2)
            : g_wsh + (size_t)cc * (SW_W / 2));
        constexpr int QUADS = SW_W / 4;
        #pragma unroll
        for (int it = 0; it < (QUADS + 511) / 512; it++) {
            int idx = tid + it * 512;
            if (QUADS % 512 == 0 || idx < QUADS)
                cp16(bufb + (uint32_t)(SX_W + idx * 4) * 4, wsrc + idx);
        }
    };

    float d[2][NT][4];
    #pragma unroll
    for (int mt = 0; mt < 2; mt++)
        #pragma unroll
        for (int nt = 0; nt < NT; nt++)
            #pragma unroll
            for (int r = 0; r < 4; r++) d[mt][nt][r] = 0.f;

    stage(0, 0);
    CP_COMMIT();

    for (int cc = 0; cc < 4; ++cc) {
        if (cc < 3) {
            stage(cc + 1, (cc + 1) & 1);
            CP_COMMIT();
            asm volatile("cp.async.wait_group 1;" ::: "memory");
        } else {
            asm volatile("cp.async.wait_group 0;" ::: "memory");
        }
        __syncthreads();

        const uint32_t* sxp = sm + (cc & 1) * BUF_W;
        const uint32_t* swp = sxp + SX_W;

        #pragma unroll
        for (int k = 0; k < 9; ++k) {
            const int dy = k / 3, dx = k % 3;
            uint32_t af[2][4];
            #pragma unroll
            for (int mt = 0; mt < 2; ++mt) {
                const int colb = colbase + mt * 16 + g + dx + 3;
                const int b0 = tig * 824 + (prow + dy) * 136 + colb;
                af[mt][0] = sxp[b0];
                af[mt][1] = sxp[b0 + 8];
                af[mt][2] = sxp[b0 + 4 * 824];
                af[mt][3] = sxp[b0 + 4 * 824 + 8];
            }
            const uint2* swq = (const uint2*)(swp + k * (NT * 64)) + lane;
            #pragma unroll
            for (int nt = 0; nt < NT; ++nt) {
                uint2 w2 = swq[nt * 32];
                mma16(d[0][nt], af[0], w2.x, w2.y);
                mma16(d[1][nt], af[1], w2.x, w2.y);
            }
        }
        __syncthreads();
    }

    // epilogue
    const int grow = R0 + prow;
    #pragma unroll
    for (int mt = 0; mt < 2; ++mt) {
        const int col = colbase + mt * 16 + g;
        float av0 = 1.f, av1 = 1.f;
        if (MODE == 0) {
            av0 = sA[prow * 128 + col];
            av1 = sA[prow * 128 + col + 8];
        }
        #pragma unroll
        for (int nt = 0; nt < NT; ++nt) {
            if (MODE == 0) {
                const int co = co_base + nt * 8 + tig * 2;
                float* o0 = outp + ((size_t)(b * 64 + co)) * HW + grow * WW + col;
                float* o1 = o0 + HW;
                o0[0] = d[mt][nt][0] * av0;
                o1[0] = d[mt][nt][1] * av0;
                o0[8] = d[mt][nt][2] * av1;
                o1[8] = d[mt][nt][3] * av1;
            } else {
                const int cp = nt * 4 + tig;
                uint32_t* hh = g_hh + ((size_t)(b * 8 + cp)) * HW + grow * WW + col;
                hh[0] = pack_h2(fmaxf(d[mt][nt][0], 0.f), fmaxf(d[mt][nt][1], 0.f));
                hh[8] = pack_h2(fmaxf(d[mt][nt][2], 0.f), fmaxf(d[mt][nt][3], 0.f));
            }
        }
    }
}

extern "C" void kernel_launch(void* const* d_in, const int* in_sizes, int n_in,
                              void* d_out, int out_size) {
    const float* x      = (const float*)d_in[0];
    const float* weight = (const float*)d_in[1];
    const float* se_w1  = (const float*)d_in[2];
    const float* se_w2  = (const float*)d_in[3];
    const float* fc_w1  = (const float*)d_in[4];
    const float* fc_w2  = (const float*)d_in[5];
    float* out = (float*)d_out;

    const int smem_main = (2 * (SX_W + 9 * 4 * 64) + 512) * 4;   // 73.2 KB -> 2 CTAs/SM
    const int smem_se   = (2 * (SX_W + 9 * 2 * 64) + 512) * 4;   // 64.0 KB -> 2 CTAs/SM
    cudaFuncSetAttribute((const void*)conv_mma<4,0>,
                         cudaFuncAttributeMaxDynamicSharedMemorySize, smem_main);
    cudaFuncSetAttribute((const void*)conv_mma<2,1>,
                         cudaFuncAttributeMaxDynamicSharedMemorySize, smem_se);

    convert_pool<<<dim3(32, BB), 256>>>(x);                          // g_xh + g_mean
    prep<<<BB, 1024>>>(fc_w1, fc_w2, weight, se_w1, se_w2);          // y + all weight frags
    conv_mma<2,1><<<dim3(32, BB), 512, smem_se>>>(nullptr);          // SE conv1 -> g_hh (fp16)
    conv_mma<4,0><<<dim3(32, BB, 2), 512, smem_main>>>(out);         // fused SE2 + main conv
}